// round 14
// baseline (speedup 1.0000x reference)
#include <cuda_runtime.h>
#include <cstdint>
#include <cstddef>

// Problem constants
#define BATCH 8
#define SEQK  8192
#define CDIM  512
#define TDIM  256
#define HEADS 8
#define DH    64

// ---------------- scratch (device globals; no allocation allowed) -----------
__device__ float g_q[TDIM * CDIM];                                  // scaled q
__device__ float g_kv[(size_t)BATCH * SEQK * 2 * CDIM];             // k|v, 268MB
__device__ float g_ctx[(size_t)BATCH * TDIM * CDIM];                // attn out
__device__ float g_y[(size_t)BATCH * TDIM * CDIM];                  // pre-LN

// ---------------- tf32 mma.sync helpers (baseline PTX, sm_80+) --------------
__device__ __forceinline__ uint32_t f2tf(float f) {
    uint32_t r;
    asm("cvt.rna.tf32.f32 %0, %1;" : "=r"(r) : "f"(f));
    return r;
}
__device__ __forceinline__ void mma_tf32(float* c, const uint32_t* a,
                                         const uint32_t* b) {
    asm volatile(
        "mma.sync.aligned.m16n8k8.row.col.f32.tf32.tf32.f32 "
        "{%0,%1,%2,%3}, {%4,%5,%6,%7}, {%8,%9}, {%0,%1,%2,%3};"
        : "+f"(c[0]), "+f"(c[1]), "+f"(c[2]), "+f"(c[3])
        : "r"(a[0]), "r"(a[1]), "r"(a[2]), "r"(a[3]), "r"(b[0]), "r"(b[1]));
}

// swizzled index into a [rows x 64] uint32 smem tile (conflict-free frag LDS)
#define PSW(r, c) (((r) << 6) + (((((c) >> 2) ^ ((r) & 7))) << 2) + ((c) & 3))

// ---------------- unified tf32 GEMM: Out = (A @ W^T + bias)*alpha + resid ----
// CTA tile 128 (M) x 64 (N), K = CDIM = 512 in chunks of 16.
// 8 warps: wm = warp>>1 (4 x 32 rows), wn = warp&1 (2 x 32 cols);
// warp tile 32x32 -> acc[2][4][4] = 32 regs/thread. 2 CTAs/SM.
// Element (r, k) of a chunk stored at smem[r*16 + (k ^ (2*(r&7)))].
__global__ void __launch_bounds__(256, 2)
gemm_tf32(const float* __restrict__ A, const float* __restrict__ W,
          const float* __restrict__ bias, float alpha,
          const float* __restrict__ resid,    // row m & 255, len CDIM (or null)
          float* __restrict__ Out, int M, int outStride)
{
    __shared__ uint32_t sA[2][128 * 16];   // 8 KB x 2
    __shared__ uint32_t sB[2][64 * 16];    // 4 KB x 2

    const int tid  = threadIdx.x;
    const int lane = tid & 31;
    const int warp = tid >> 5;
    const int wm   = warp >> 1;          // 0..3 (32-row slab)
    const int wn   = warp & 1;           // 0..1 (32-col slab)
    const int m0   = blockIdx.y * 128;
    const int n0   = blockIdx.x * 64;

    const int lr = tid >> 2;             // 0..63
    const int lk = (tid & 3) * 4;        // 0,4,8,12

    const float* Ag0 = A + (size_t)(m0 + lr) * CDIM + lk;
    const float* Ag1 = Ag0 + (size_t)64 * CDIM;
    const float* Bg0 = W + (size_t)(n0 + lr) * CDIM + lk;   // lr < 64 rows of B

    auto sts4 = [&](uint32_t* sm, int r, float4 v) {
        const int c = 2 * (r & 7);
        const int base = r * 16 + (lk ^ (c & 12));
        const int o = c & 2;
        sm[base + o]           = f2tf(v.x);
        sm[base + o + 1]       = f2tf(v.y);
        sm[base + (2 - o)]     = f2tf(v.z);
        sm[base + (2 - o) + 1] = f2tf(v.w);
    };

    float acc[2][4][4];
#pragma unroll
    for (int i = 0; i < 2; i++)
#pragma unroll
        for (int j = 0; j < 4; j++)
#pragma unroll
            for (int t = 0; t < 4; t++) acc[i][j][t] = 0.0f;

    // prologue: chunk 0
    {
        float4 a0 = *(const float4*)Ag0;
        float4 a1 = *(const float4*)Ag1;
        float4 b0 = *(const float4*)Bg0;
        sts4(sA[0], lr, a0); sts4(sA[0], lr + 64, a1);
        sts4(sB[0], lr, b0);
    }
    __syncthreads();

    const int q  = lane >> 2;            // 0..7
    const int kk = lane & 3;             // 0..3
    const int cx = 2 * q;

    const int NIT = CDIM / 16;           // 32
    for (int it = 0; it < NIT; it++) {
        const int buf = it & 1;
        float4 ra0, ra1, rb0;
        if (it + 1 < NIT) {
            const int ko = (it + 1) * 16;
            ra0 = *(const float4*)(Ag0 + ko);
            ra1 = *(const float4*)(Ag1 + ko);
            rb0 = *(const float4*)(Bg0 + ko);
        }
        const uint32_t* sAb = sA[buf];
        const uint32_t* sBb = sB[buf];
#pragma unroll
        for (int ks = 0; ks < 2; ks++) {
            const int ka = ((ks << 3) + kk) ^ cx;
            const int kb = ka ^ 4;
            uint32_t af[2][4], bf[4][2];
#pragma unroll
            for (int mt = 0; mt < 2; mt++) {
                const int rb_ = (wm * 32 + mt * 16 + q) * 16;
                af[mt][0] = sAb[rb_ + ka];
                af[mt][1] = sAb[rb_ + 128 + ka];
                af[mt][2] = sAb[rb_ + kb];
                af[mt][3] = sAb[rb_ + 128 + kb];
            }
#pragma unroll
            for (int nt = 0; nt < 4; nt++) {
                const int rn = (wn * 32 + nt * 8 + q) * 16;
                bf[nt][0] = sBb[rn + ka];
                bf[nt][1] = sBb[rn + kb];
            }
#pragma unroll
            for (int mt = 0; mt < 2; mt++)
#pragma unroll
                for (int nt = 0; nt < 4; nt++)
                    mma_tf32(acc[mt][nt], af[mt], bf[nt]);
        }
        if (it + 1 < NIT) {
            const int nb = buf ^ 1;
            sts4(sA[nb], lr, ra0); sts4(sA[nb], lr + 64, ra1);
            sts4(sB[nb], lr, rb0);
            __syncthreads();
        }
    }

    // epilogue: c0/c1 -> (row q, cols 2kk,2kk+1); c2/c3 -> row q+8
#pragma unroll
    for (int mt = 0; mt < 2; mt++) {
        const int m = m0 + wm * 32 + mt * 16 + q;
#pragma unroll
        for (int nt = 0; nt < 4; nt++) {
            const int n = n0 + wn * 32 + nt * 8 + 2 * kk;
            const float bx = bias[n], by = bias[n + 1];
            float2 o0 = make_float2((acc[mt][nt][0] + bx) * alpha,
                                    (acc[mt][nt][1] + by) * alpha);
            float2 o1 = make_float2((acc[mt][nt][2] + bx) * alpha,
                                    (acc[mt][nt][3] + by) * alpha);
            if (resid) {
                const float* r0 = resid + (size_t)(m & (TDIM - 1)) * CDIM;
                const float* r1 = resid + (size_t)((m + 8) & (TDIM - 1)) * CDIM;
                o0.x += r0[n]; o0.y += r0[n + 1];
                o1.x += r1[n]; o1.y += r1[n + 1];
            }
            *(float2*)(Out + (size_t)m * outStride + n) = o0;
            *(float2*)(Out + (size_t)(m + 8) * outStride + n) = o1;
        }
    }
}

// ---------------- flash attention via mma.sync tf32 (unchanged, passing) ----
// CTA = (128-query tile, head, batch); 8 warps x 16 query rows.
// smem (dynamic 64KB): sK[64x64] | sVt[64x64] | sP[128x64] (sP doubles as Q stage)
__global__ void __launch_bounds__(256)
attn_mma(const float* __restrict__ q, const float* __restrict__ kv,
         float* __restrict__ ctx)
{
    extern __shared__ uint32_t sm[];
    uint32_t* sK  = sm;           // 64*64
    uint32_t* sVt = sm + 4096;    // 64*64 (V transposed: [dh][key])
    uint32_t* sP  = sm + 8192;    // 128*64

    const int tid  = threadIdx.x;
    const int lane = tid & 31;
    const int w    = tid >> 5;
    const int qr   = lane >> 2;      // 0..7
    const int kk   = lane & 3;       // 0..3
    const int t0   = blockIdx.x * 128;
    const int h    = blockIdx.y;
    const int b    = blockIdx.z;
    const int r0   = w * 16 + qr;

    // stage Q tile (pre-scaled by 1/8 in q-proj) into sP, swizzled tf32
    {
        const int r  = tid >> 1;
        const int cb = (tid & 1) * 32;
        const float* qrow = q + (size_t)(t0 + r) * CDIM + h * DH + cb;
#pragma unroll
        for (int j = 0; j < 8; j++) {
            float4 v = *(const float4*)(qrow + j * 4);
            const int c4 = (((cb >> 2) + j) ^ (r & 7)) << 2;
            uint32_t* d = sP + r * 64 + c4;
            d[0] = f2tf(v.x); d[1] = f2tf(v.y); d[2] = f2tf(v.z); d[3] = f2tf(v.w);
        }
    }
    __syncthreads();

    // Q fragments live in registers for the whole kernel
    uint32_t qa[8][4];
#pragma unroll
    for (int ks = 0; ks < 8; ks++) {
        qa[ks][0] = sP[PSW(r0,     kk + 8 * ks)];
        qa[ks][1] = sP[PSW(r0 + 8, kk + 8 * ks)];
        qa[ks][2] = sP[PSW(r0,     kk + 4 + 8 * ks)];
        qa[ks][3] = sP[PSW(r0 + 8, kk + 4 + 8 * ks)];
    }
    // (the in-loop syncs order these reads before any P write to sP)

    float o[8][4];
#pragma unroll
    for (int nt = 0; nt < 8; nt++)
#pragma unroll
        for (int t = 0; t < 4; t++) o[nt][t] = 0.0f;
    float m0 = -1e30f, m1 = -1e30f, l0 = 0.0f, l1 = 0.0f;

    const float* kvb = kv + (size_t)b * SEQK * (2 * CDIM) + h * DH;
    const int kr = tid >> 2;         // 0..63 key row
    const int kq = tid & 3;          // 16-col group

    float4 kreg[4], vreg[4];
    {
        const float* krow = kvb + (size_t)kr * (2 * CDIM) + kq * 16;
#pragma unroll
        for (int j = 0; j < 4; j++) {
            kreg[j] = *(const float4*)(krow + j * 4);
            vreg[j] = *(const float4*)(krow + CDIM + j * 4);
        }
    }

    for (int c = 0; c < SEQK / 64; c++) {
        if (c) __syncthreads();      // prior chunk's mma reads done
        // STS K (swizzled uint4)
#pragma unroll
        for (int j = 0; j < 4; j++) {
            const int c4 = ((kq * 4 + j) ^ (kr & 7)) << 2;
            uint32_t* d = sK + kr * 64 + c4;
            d[0] = f2tf(kreg[j].x); d[1] = f2tf(kreg[j].y);
            d[2] = f2tf(kreg[j].z); d[3] = f2tf(kreg[j].w);
        }
        // STS V transposed (rotation over kq keeps banks distinct)
        {
            const float* vf = (const float*)vreg;
#pragma unroll
            for (int i = 0; i < 16; i++) {
                const int idx = (i + kq * 2) & 15;
                const int dd = kq * 16 + idx;
                sVt[PSW(dd, kr)] = f2tf(vf[idx]);
            }
        }
        // prefetch next chunk into registers (overlaps mma section)
        if (c + 1 < SEQK / 64) {
            const float* krow = kvb + (size_t)((c + 1) * 64 + kr) * (2 * CDIM) + kq * 16;
#pragma unroll
            for (int j = 0; j < 4; j++) {
                kreg[j] = *(const float4*)(krow + j * 4);
                vreg[j] = *(const float4*)(krow + CDIM + j * 4);
            }
        }
        __syncthreads();

        // S = Q K^T : rows r0,r0+8; cols = 64 keys (8 n-tiles)
        float sc[8][4];
#pragma unroll
        for (int nt = 0; nt < 8; nt++)
#pragma unroll
            for (int t = 0; t < 4; t++) sc[nt][t] = 0.0f;
#pragma unroll
        for (int ks = 0; ks < 8; ks++) {
#pragma unroll
            for (int nt = 0; nt < 8; nt++) {
                uint32_t bf[2];
                bf[0] = sK[PSW(nt * 8 + qr, kk + 8 * ks)];
                bf[1] = sK[PSW(nt * 8 + qr, kk + 4 + 8 * ks)];
                mma_tf32(sc[nt], qa[ks], bf);
            }
        }

        // online softmax over this chunk (quad lanes share a row)
        float mx0 = -1e30f, mx1 = -1e30f;
#pragma unroll
        for (int nt = 0; nt < 8; nt++) {
            mx0 = fmaxf(mx0, fmaxf(sc[nt][0], sc[nt][1]));
            mx1 = fmaxf(mx1, fmaxf(sc[nt][2], sc[nt][3]));
        }
        mx0 = fmaxf(mx0, __shfl_xor_sync(0xffffffffu, mx0, 1));
        mx0 = fmaxf(mx0, __shfl_xor_sync(0xffffffffu, mx0, 2));
        mx1 = fmaxf(mx1, __shfl_xor_sync(0xffffffffu, mx1, 1));
        mx1 = fmaxf(mx1, __shfl_xor_sync(0xffffffffu, mx1, 2));
        const float m0n = fmaxf(m0, mx0), m1n = fmaxf(m1, mx1);
        const float al0 = __expf(m0 - m0n), al1 = __expf(m1 - m1n);
        float s0 = 0.0f, s1 = 0.0f;
#pragma unroll
        for (int nt = 0; nt < 8; nt++) {
            sc[nt][0] = __expf(sc[nt][0] - m0n);
            sc[nt][1] = __expf(sc[nt][1] - m0n);
            sc[nt][2] = __expf(sc[nt][2] - m1n);
            sc[nt][3] = __expf(sc[nt][3] - m1n);
            s0 += sc[nt][0] + sc[nt][1];
            s1 += sc[nt][2] + sc[nt][3];
        }
        s0 += __shfl_xor_sync(0xffffffffu, s0, 1);
        s0 += __shfl_xor_sync(0xffffffffu, s0, 2);
        s1 += __shfl_xor_sync(0xffffffffu, s1, 1);
        s1 += __shfl_xor_sync(0xffffffffu, s1, 2);
        l0 = l0 * al0 + s0;  l1 = l1 * al1 + s1;
        m0 = m0n;  m1 = m1n;
#pragma unroll
        for (int nt = 0; nt < 8; nt++) {
            o[nt][0] *= al0; o[nt][1] *= al0;
            o[nt][2] *= al1; o[nt][3] *= al1;
        }

        // write P (tf32, swizzled) for the PV mma
#pragma unroll
        for (int nt = 0; nt < 8; nt++) {
            const int cb = nt * 8 + 2 * kk;
            sP[PSW(r0, cb)]         = f2tf(sc[nt][0]);
            sP[PSW(r0, cb + 1)]     = f2tf(sc[nt][1]);
            sP[PSW(r0 + 8, cb)]     = f2tf(sc[nt][2]);
            sP[PSW(r0 + 8, cb + 1)] = f2tf(sc[nt][3]);
        }
        __syncthreads();

        // O += P V  (contraction over 64 keys)
#pragma unroll
        for (int ks = 0; ks < 8; ks++) {
            uint32_t af[4];
            af[0] = sP[PSW(r0,     kk + 8 * ks)];
            af[1] = sP[PSW(r0 + 8, kk + 8 * ks)];
            af[2] = sP[PSW(r0,     kk + 4 + 8 * ks)];
            af[3] = sP[PSW(r0 + 8, kk + 4 + 8 * ks)];
#pragma unroll
            for (int nt = 0; nt < 8; nt++) {
                uint32_t bf[2];
                bf[0] = sVt[PSW(nt * 8 + qr, kk + 8 * ks)];
                bf[1] = sVt[PSW(nt * 8 + qr, kk + 4 + 8 * ks)];
                mma_tf32(o[nt], af, bf);
            }
        }
    }

    // epilogue: ctx = O / l
    const float i0 = 1.0f / l0, i1 = 1.0f / l1;
    float* crow0 = ctx + (size_t)(b * TDIM + t0 + r0) * CDIM + h * DH;
    float* crow1 = crow0 + (size_t)8 * CDIM;
#pragma unroll
    for (int nt = 0; nt < 8; nt++) {
        const int cb = nt * 8 + 2 * kk;
        *(float2*)(crow0 + cb) = make_float2(o[nt][0] * i0, o[nt][1] * i0);
        *(float2*)(crow1 + cb) = make_float2(o[nt][2] * i1, o[nt][3] * i1);
    }
}

// ---------------- LayerNorm over C=512 -------------------------------------
__global__ void __launch_bounds__(256)
ln_kernel(const float* __restrict__ y, const float* __restrict__ gamma,
          const float* __restrict__ beta, float* __restrict__ out)
{
    __shared__ float2 sred[8];
    const int row = blockIdx.x;
    const int tid = threadIdx.x;
    const float* yr = y + (size_t)row * CDIM;
    float2 v = *(const float2*)(yr + tid * 2);
    float s1 = v.x + v.y;
    float s2 = v.x * v.x + v.y * v.y;
#pragma unroll
    for (int o = 16; o > 0; o >>= 1) {
        s1 += __shfl_xor_sync(0xffffffffu, s1, o);
        s2 += __shfl_xor_sync(0xffffffffu, s2, o);
    }
    if ((tid & 31) == 0) sred[tid >> 5] = make_float2(s1, s2);
    __syncthreads();
    float t1 = 0.f, t2 = 0.f;
#pragma unroll
    for (int i = 0; i < 8; i++) { t1 += sred[i].x; t2 += sred[i].y; }
    const float mean = t1 * (1.0f / CDIM);
    const float var  = t2 * (1.0f / CDIM) - mean * mean;
    const float rstd = rsqrtf(var + 1e-5f);
    const int c = tid * 2;
    float2 g = *(const float2*)(gamma + c);
    float2 be = *(const float2*)(beta + c);
    float2 o;
    o.x = (v.x - mean) * rstd * g.x + be.x;
    o.y = (v.y - mean) * rstd * g.y + be.y;
    *(float2*)(out + (size_t)row * CDIM + c) = o;
}

// ---------------- launch ----------------------------------------------------
extern "C" void kernel_launch(void* const* d_in, const int* in_sizes, int n_in,
                              void* d_out, int out_size) {
    const float* x   = (const float*)d_in[0];
    const float* qt  = (const float*)d_in[1];
    const float* ipw = (const float*)d_in[2];
    const float* ipb = (const float*)d_in[3];
    const float* opw = (const float*)d_in[4];
    const float* opb = (const float*)d_in[5];
    const float* lng = (const float*)d_in[6];
    const float* lnb = (const float*)d_in[7];
    float* out = (float*)d_out;

    float *pq, *pkv, *pctx, *py;
    cudaGetSymbolAddress((void**)&pq,  g_q);
    cudaGetSymbolAddress((void**)&pkv, g_kv);
    cudaGetSymbolAddress((void**)&pctx, g_ctx);
    cudaGetSymbolAddress((void**)&py,  g_y);

    cudaFuncSetAttribute(attn_mma, cudaFuncAttributeMaxDynamicSharedMemorySize,
                         65536);

    // 1) q projection (scale 1/sqrt(64) baked in): [256,512]
    gemm_tf32<<<dim3(8, 2), 256>>>(qt, ipw, ipb, 0.125f, nullptr,
                                   pq, TDIM, CDIM);
    // 2) kv projection: [65536,1024] = x @ [Wk;Wv]^T + [bk;bv]
    gemm_tf32<<<dim3(16, 512), 256>>>(x, ipw + CDIM * CDIM, ipb + CDIM, 1.0f,
                                      nullptr, pkv, BATCH * SEQK, 2 * CDIM);
    // 3) fused flash attention via mma.sync tf32 -> ctx
    attn_mma<<<dim3(TDIM / 128, HEADS, BATCH), 256, 65536>>>(pq, pkv, pctx);
    // 4) out projection + residual: [2048,512]
    gemm_tf32<<<dim3(8, 16), 256>>>(pctx, opw, opb, 1.0f, qt,
                                    py, BATCH * TDIM, CDIM);
    // 5) layernorm -> out
    ln_kernel<<<BATCH * TDIM, 256>>>(py, lng, lnb, out);
}

// round 15
// speedup vs baseline: 1.0299x; 1.0299x over previous
#include <cuda_runtime.h>
#include <cstdint>
#include <cstddef>

// Problem constants
#define BATCH 8
#define SEQK  8192
#define CDIM  512
#define TDIM  256
#define HEADS 8
#define DH    64

// ---------------- scratch (device globals; no allocation allowed) -----------
__device__ float g_q[TDIM * CDIM];                                  // scaled q
__device__ float g_kv[(size_t)BATCH * SEQK * 2 * CDIM];             // k|v, 268MB
__device__ float g_ctx[(size_t)BATCH * TDIM * CDIM];                // attn out
__device__ float g_y[(size_t)BATCH * TDIM * CDIM];                  // pre-LN

// ---------------- tf32 mma.sync helpers (baseline PTX, sm_80+) --------------
__device__ __forceinline__ uint32_t f2tf(float f) {
    uint32_t r;
    asm("cvt.rna.tf32.f32 %0, %1;" : "=r"(r) : "f"(f));
    return r;
}
__device__ __forceinline__ void mma_tf32(float* c, const uint32_t* a,
                                         const uint32_t* b) {
    asm volatile(
        "mma.sync.aligned.m16n8k8.row.col.f32.tf32.tf32.f32 "
        "{%0,%1,%2,%3}, {%4,%5,%6,%7}, {%8,%9}, {%0,%1,%2,%3};"
        : "+f"(c[0]), "+f"(c[1]), "+f"(c[2]), "+f"(c[3])
        : "r"(a[0]), "r"(a[1]), "r"(a[2]), "r"(a[3]), "r"(b[0]), "r"(b[1]));
}

// swizzled index into a [rows x 64] uint32 smem tile (conflict-free frag LDS)
#define PSW(r, c) (((r) << 6) + (((((c) >> 2) ^ ((r) & 7))) << 2) + ((c) & 3))

// ---------------- unified tf32 GEMM: Out = (A @ W^T + bias)*alpha + resid ----
// CTA tile 128 (M) x 128 (N), K = CDIM = 512 in chunks of 16, 512 threads.
// 16 warps: wm = warp>>2 (4 x 32 rows), wn = warp&3 (4 x 32 cols);
// warp tile 32x32 -> acc[2][4][4] = 32 regs/thread (104 regs measured in R14).
// 16 warps/SM = 4 warps/SMSP: 2x R14's latency-hiding.
// Element (r, k) of a chunk stored at smem[r*16 + (k ^ (2*(r&7)))].
__global__ void __launch_bounds__(512, 1)
gemm_tf32(const float* __restrict__ A, const float* __restrict__ W,
          const float* __restrict__ bias, float alpha,
          const float* __restrict__ resid,    // row m & 255, len CDIM (or null)
          float* __restrict__ Out, int M, int outStride)
{
    __shared__ uint32_t sA[2][128 * 16];   // 8 KB x 2
    __shared__ uint32_t sB[2][128 * 16];   // 8 KB x 2

    const int tid  = threadIdx.x;
    const int lane = tid & 31;
    const int warp = tid >> 5;
    const int wm   = warp >> 2;          // 0..3 (32-row slab)
    const int wn   = warp & 3;           // 0..3 (32-col slab)
    const int m0   = blockIdx.y * 128;
    const int n0   = blockIdx.x * 128;

    const int lr = tid >> 2;             // 0..127
    const int lk = (tid & 3) * 4;        // 0,4,8,12

    const float* Ag = A + (size_t)(m0 + lr) * CDIM + lk;
    const float* Bg = W + (size_t)(n0 + lr) * CDIM + lk;

    auto sts4 = [&](uint32_t* sm, int r, float4 v) {
        const int c = 2 * (r & 7);
        const int base = r * 16 + (lk ^ (c & 12));
        const int o = c & 2;
        sm[base + o]           = f2tf(v.x);
        sm[base + o + 1]       = f2tf(v.y);
        sm[base + (2 - o)]     = f2tf(v.z);
        sm[base + (2 - o) + 1] = f2tf(v.w);
    };

    float acc[2][4][4];
#pragma unroll
    for (int i = 0; i < 2; i++)
#pragma unroll
        for (int j = 0; j < 4; j++)
#pragma unroll
            for (int t = 0; t < 4; t++) acc[i][j][t] = 0.0f;

    // prologue: chunk 0 (one float4 of A and one of B per thread)
    {
        float4 a0 = *(const float4*)Ag;
        float4 b0 = *(const float4*)Bg;
        sts4(sA[0], lr, a0);
        sts4(sB[0], lr, b0);
    }
    __syncthreads();

    const int q  = lane >> 2;            // 0..7
    const int kk = lane & 3;             // 0..3
    const int cx = 2 * q;

    const int NIT = CDIM / 16;           // 32
    for (int it = 0; it < NIT; it++) {
        const int buf = it & 1;
        float4 ra, rb;
        if (it + 1 < NIT) {
            const int ko = (it + 1) * 16;
            ra = *(const float4*)(Ag + ko);
            rb = *(const float4*)(Bg + ko);
        }
        const uint32_t* sAb = sA[buf];
        const uint32_t* sBb = sB[buf];
#pragma unroll
        for (int ks = 0; ks < 2; ks++) {
            const int ka = ((ks << 3) + kk) ^ cx;
            const int kb = ka ^ 4;
            uint32_t af[2][4], bf[4][2];
#pragma unroll
            for (int mt = 0; mt < 2; mt++) {
                const int rb_ = (wm * 32 + mt * 16 + q) * 16;
                af[mt][0] = sAb[rb_ + ka];
                af[mt][1] = sAb[rb_ + 128 + ka];
                af[mt][2] = sAb[rb_ + kb];
                af[mt][3] = sAb[rb_ + 128 + kb];
            }
#pragma unroll
            for (int nt = 0; nt < 4; nt++) {
                const int rn = (wn * 32 + nt * 8 + q) * 16;
                bf[nt][0] = sBb[rn + ka];
                bf[nt][1] = sBb[rn + kb];
            }
#pragma unroll
            for (int mt = 0; mt < 2; mt++)
#pragma unroll
                for (int nt = 0; nt < 4; nt++)
                    mma_tf32(acc[mt][nt], af[mt], bf[nt]);
        }
        if (it + 1 < NIT) {
            const int nb = buf ^ 1;
            sts4(sA[nb], lr, ra);
            sts4(sB[nb], lr, rb);
            __syncthreads();
        }
    }

    // epilogue: c0/c1 -> (row q, cols 2kk,2kk+1); c2/c3 -> row q+8
#pragma unroll
    for (int mt = 0; mt < 2; mt++) {
        const int m = m0 + wm * 32 + mt * 16 + q;
#pragma unroll
        for (int nt = 0; nt < 4; nt++) {
            const int n = n0 + wn * 32 + nt * 8 + 2 * kk;
            const float bx = bias[n], by = bias[n + 1];
            float2 o0 = make_float2((acc[mt][nt][0] + bx) * alpha,
                                    (acc[mt][nt][1] + by) * alpha);
            float2 o1 = make_float2((acc[mt][nt][2] + bx) * alpha,
                                    (acc[mt][nt][3] + by) * alpha);
            if (resid) {
                const float* r0 = resid + (size_t)(m & (TDIM - 1)) * CDIM;
                const float* r1 = resid + (size_t)((m + 8) & (TDIM - 1)) * CDIM;
                o0.x += r0[n]; o0.y += r0[n + 1];
                o1.x += r1[n]; o1.y += r1[n + 1];
            }
            *(float2*)(Out + (size_t)m * outStride + n) = o0;
            *(float2*)(Out + (size_t)(m + 8) * outStride + n) = o1;
        }
    }
}

// ---------------- flash attention via mma.sync tf32 (unchanged, passing) ----
// CTA = (128-query tile, head, batch); 8 warps x 16 query rows.
// smem (dynamic 64KB): sK[64x64] | sVt[64x64] | sP[128x64] (sP doubles as Q stage)
__global__ void __launch_bounds__(256)
attn_mma(const float* __restrict__ q, const float* __restrict__ kv,
         float* __restrict__ ctx)
{
    extern __shared__ uint32_t sm[];
    uint32_t* sK  = sm;           // 64*64
    uint32_t* sVt = sm + 4096;    // 64*64 (V transposed: [dh][key])
    uint32_t* sP  = sm + 8192;    // 128*64

    const int tid  = threadIdx.x;
    const int lane = tid & 31;
    const int w    = tid >> 5;
    const int qr   = lane >> 2;      // 0..7
    const int kk   = lane & 3;       // 0..3
    const int t0   = blockIdx.x * 128;
    const int h    = blockIdx.y;
    const int b    = blockIdx.z;
    const int r0   = w * 16 + qr;

    // stage Q tile (pre-scaled by 1/8 in q-proj) into sP, swizzled tf32
    {
        const int r  = tid >> 1;
        const int cb = (tid & 1) * 32;
        const float* qrow = q + (size_t)(t0 + r) * CDIM + h * DH + cb;
#pragma unroll
        for (int j = 0; j < 8; j++) {
            float4 v = *(const float4*)(qrow + j * 4);
            const int c4 = (((cb >> 2) + j) ^ (r & 7)) << 2;
            uint32_t* d = sP + r * 64 + c4;
            d[0] = f2tf(v.x); d[1] = f2tf(v.y); d[2] = f2tf(v.z); d[3] = f2tf(v.w);
        }
    }
    __syncthreads();

    // Q fragments live in registers for the whole kernel
    uint32_t qa[8][4];
#pragma unroll
    for (int ks = 0; ks < 8; ks++) {
        qa[ks][0] = sP[PSW(r0,     kk + 8 * ks)];
        qa[ks][1] = sP[PSW(r0 + 8, kk + 8 * ks)];
        qa[ks][2] = sP[PSW(r0,     kk + 4 + 8 * ks)];
        qa[ks][3] = sP[PSW(r0 + 8, kk + 4 + 8 * ks)];
    }
    // (the in-loop syncs order these reads before any P write to sP)

    float o[8][4];
#pragma unroll
    for (int nt = 0; nt < 8; nt++)
#pragma unroll
        for (int t = 0; t < 4; t++) o[nt][t] = 0.0f;
    float m0 = -1e30f, m1 = -1e30f, l0 = 0.0f, l1 = 0.0f;

    const float* kvb = kv + (size_t)b * SEQK * (2 * CDIM) + h * DH;
    const int kr = tid >> 2;         // 0..63 key row
    const int kq = tid & 3;          // 16-col group

    float4 kreg[4], vreg[4];
    {
        const float* krow = kvb + (size_t)kr * (2 * CDIM) + kq * 16;
#pragma unroll
        for (int j = 0; j < 4; j++) {
            kreg[j] = *(const float4*)(krow + j * 4);
            vreg[j] = *(const float4*)(krow + CDIM + j * 4);
        }
    }

    for (int c = 0; c < SEQK / 64; c++) {
        if (c) __syncthreads();      // prior chunk's mma reads done
        // STS K (swizzled uint4)
#pragma unroll
        for (int j = 0; j < 4; j++) {
            const int c4 = ((kq * 4 + j) ^ (kr & 7)) << 2;
            uint32_t* d = sK + kr * 64 + c4;
            d[0] = f2tf(kreg[j].x); d[1] = f2tf(kreg[j].y);
            d[2] = f2tf(kreg[j].z); d[3] = f2tf(kreg[j].w);
        }
        // STS V transposed (rotation over kq keeps banks distinct)
        {
            const float* vf = (const float*)vreg;
#pragma unroll
            for (int i = 0; i < 16; i++) {
                const int idx = (i + kq * 2) & 15;
                const int dd = kq * 16 + idx;
                sVt[PSW(dd, kr)] = f2tf(vf[idx]);
            }
        }
        // prefetch next chunk into registers (overlaps mma section)
        if (c + 1 < SEQK / 64) {
            const float* krow = kvb + (size_t)((c + 1) * 64 + kr) * (2 * CDIM) + kq * 16;
#pragma unroll
            for (int j = 0; j < 4; j++) {
                kreg[j] = *(const float4*)(krow + j * 4);
                vreg[j] = *(const float4*)(krow + CDIM + j * 4);
            }
        }
        __syncthreads();

        // S = Q K^T : rows r0,r0+8; cols = 64 keys (8 n-tiles)
        float sc[8][4];
#pragma unroll
        for (int nt = 0; nt < 8; nt++)
#pragma unroll
            for (int t = 0; t < 4; t++) sc[nt][t] = 0.0f;
#pragma unroll
        for (int ks = 0; ks < 8; ks++) {
#pragma unroll
            for (int nt = 0; nt < 8; nt++) {
                uint32_t bf[2];
                bf[0] = sK[PSW(nt * 8 + qr, kk + 8 * ks)];
                bf[1] = sK[PSW(nt * 8 + qr, kk + 4 + 8 * ks)];
                mma_tf32(sc[nt], qa[ks], bf);
            }
        }

        // online softmax over this chunk (quad lanes share a row)
        float mx0 = -1e30f, mx1 = -1e30f;
#pragma unroll
        for (int nt = 0; nt < 8; nt++) {
            mx0 = fmaxf(mx0, fmaxf(sc[nt][0], sc[nt][1]));
            mx1 = fmaxf(mx1, fmaxf(sc[nt][2], sc[nt][3]));
        }
        mx0 = fmaxf(mx0, __shfl_xor_sync(0xffffffffu, mx0, 1));
        mx0 = fmaxf(mx0, __shfl_xor_sync(0xffffffffu, mx0, 2));
        mx1 = fmaxf(mx1, __shfl_xor_sync(0xffffffffu, mx1, 1));
        mx1 = fmaxf(mx1, __shfl_xor_sync(0xffffffffu, mx1, 2));
        const float m0n = fmaxf(m0, mx0), m1n = fmaxf(m1, mx1);
        const float al0 = __expf(m0 - m0n), al1 = __expf(m1 - m1n);
        float s0 = 0.0f, s1 = 0.0f;
#pragma unroll
        for (int nt = 0; nt < 8; nt++) {
            sc[nt][0] = __expf(sc[nt][0] - m0n);
            sc[nt][1] = __expf(sc[nt][1] - m0n);
            sc[nt][2] = __expf(sc[nt][2] - m1n);
            sc[nt][3] = __expf(sc[nt][3] - m1n);
            s0 += sc[nt][0] + sc[nt][1];
            s1 += sc[nt][2] + sc[nt][3];
        }
        s0 += __shfl_xor_sync(0xffffffffu, s0, 1);
        s0 += __shfl_xor_sync(0xffffffffu, s0, 2);
        s1 += __shfl_xor_sync(0xffffffffu, s1, 1);
        s1 += __shfl_xor_sync(0xffffffffu, s1, 2);
        l0 = l0 * al0 + s0;  l1 = l1 * al1 + s1;
        m0 = m0n;  m1 = m1n;
#pragma unroll
        for (int nt = 0; nt < 8; nt++) {
            o[nt][0] *= al0; o[nt][1] *= al0;
            o[nt][2] *= al1; o[nt][3] *= al1;
        }

        // write P (tf32, swizzled) for the PV mma
#pragma unroll
        for (int nt = 0; nt < 8; nt++) {
            const int cb = nt * 8 + 2 * kk;
            sP[PSW(r0, cb)]         = f2tf(sc[nt][0]);
            sP[PSW(r0, cb + 1)]     = f2tf(sc[nt][1]);
            sP[PSW(r0 + 8, cb)]     = f2tf(sc[nt][2]);
            sP[PSW(r0 + 8, cb + 1)] = f2tf(sc[nt][3]);
        }
        __syncthreads();

        // O += P V  (contraction over 64 keys)
#pragma unroll
        for (int ks = 0; ks < 8; ks++) {
            uint32_t af[4];
            af[0] = sP[PSW(r0,     kk + 8 * ks)];
            af[1] = sP[PSW(r0 + 8, kk + 8 * ks)];
            af[2] = sP[PSW(r0,     kk + 4 + 8 * ks)];
            af[3] = sP[PSW(r0 + 8, kk + 4 + 8 * ks)];
#pragma unroll
            for (int nt = 0; nt < 8; nt++) {
                uint32_t bf[2];
                bf[0] = sVt[PSW(nt * 8 + qr, kk + 8 * ks)];
                bf[1] = sVt[PSW(nt * 8 + qr, kk + 4 + 8 * ks)];
                mma_tf32(o[nt], af, bf);
            }
        }
    }

    // epilogue: ctx = O / l
    const float i0 = 1.0f / l0, i1 = 1.0f / l1;
    float* crow0 = ctx + (size_t)(b * TDIM + t0 + r0) * CDIM + h * DH;
    float* crow1 = crow0 + (size_t)8 * CDIM;
#pragma unroll
    for (int nt = 0; nt < 8; nt++) {
        const int cb = nt * 8 + 2 * kk;
        *(float2*)(crow0 + cb) = make_float2(o[nt][0] * i0, o[nt][1] * i0);
        *(float2*)(crow1 + cb) = make_float2(o[nt][2] * i1, o[nt][3] * i1);
    }
}

// ---------------- LayerNorm over C=512 -------------------------------------
__global__ void __launch_bounds__(256)
ln_kernel(const float* __restrict__ y, const float* __restrict__ gamma,
          const float* __restrict__ beta, float* __restrict__ out)
{
    __shared__ float2 sred[8];
    const int row = blockIdx.x;
    const int tid = threadIdx.x;
    const float* yr = y + (size_t)row * CDIM;
    float2 v = *(const float2*)(yr + tid * 2);
    float s1 = v.x + v.y;
    float s2 = v.x * v.x + v.y * v.y;
#pragma unroll
    for (int o = 16; o > 0; o >>= 1) {
        s1 += __shfl_xor_sync(0xffffffffu, s1, o);
        s2 += __shfl_xor_sync(0xffffffffu, s2, o);
    }
    if ((tid & 31) == 0) sred[tid >> 5] = make_float2(s1, s2);
    __syncthreads();
    float t1 = 0.f, t2 = 0.f;
#pragma unroll
    for (int i = 0; i < 8; i++) { t1 += sred[i].x; t2 += sred[i].y; }
    const float mean = t1 * (1.0f / CDIM);
    const float var  = t2 * (1.0f / CDIM) - mean * mean;
    const float rstd = rsqrtf(var + 1e-5f);
    const int c = tid * 2;
    float2 g = *(const float2*)(gamma + c);
    float2 be = *(const float2*)(beta + c);
    float2 o;
    o.x = (v.x - mean) * rstd * g.x + be.x;
    o.y = (v.y - mean) * rstd * g.y + be.y;
    *(float2*)(out + (size_t)row * CDIM + c) = o;
}

// ---------------- launch ----------------------------------------------------
extern "C" void kernel_launch(void* const* d_in, const int* in_sizes, int n_in,
                              void* d_out, int out_size) {
    const float* x   = (const float*)d_in[0];
    const float* qt  = (const float*)d_in[1];
    const float* ipw = (const float*)d_in[2];
    const float* ipb = (const float*)d_in[3];
    const float* opw = (const float*)d_in[4];
    const float* opb = (const float*)d_in[5];
    const float* lng = (const float*)d_in[6];
    const float* lnb = (const float*)d_in[7];
    float* out = (float*)d_out;

    float *pq, *pkv, *pctx, *py;
    cudaGetSymbolAddress((void**)&pq,  g_q);
    cudaGetSymbolAddress((void**)&pkv, g_kv);
    cudaGetSymbolAddress((void**)&pctx, g_ctx);
    cudaGetSymbolAddress((void**)&py,  g_y);

    cudaFuncSetAttribute(attn_mma, cudaFuncAttributeMaxDynamicSharedMemorySize,
                         65536);

    // 1) q projection (scale 1/sqrt(64) baked in): [256,512]
    gemm_tf32<<<dim3(4, 2), 512>>>(qt, ipw, ipb, 0.125f, nullptr,
                                   pq, TDIM, CDIM);
    // 2) kv projection: [65536,1024] = x @ [Wk;Wv]^T + [bk;bv]
    gemm_tf32<<<dim3(8, 512), 512>>>(x, ipw + CDIM * CDIM, ipb + CDIM, 1.0f,
                                     nullptr, pkv, BATCH * SEQK, 2 * CDIM);
    // 3) fused flash attention via mma.sync tf32 -> ctx
    attn_mma<<<dim3(TDIM / 128, HEADS, BATCH), 256, 65536>>>(pq, pkv, pctx);
    // 4) out projection + residual: [2048,512]
    gemm_tf32<<<dim3(4, 16), 512>>>(pctx, opw, opb, 1.0f, qt,
                                    py, BATCH * TDIM, CDIM);
    // 5) layernorm -> out
    ln_kernel<<<BATCH * TDIM, 256>>>(py, lng, lnb, out);
}